// round 9
// baseline (speedup 1.0000x reference)
#include <cuda_runtime.h>
#include <cuda_fp16.h>
#include <math.h>

#define MIN_ROUGHNESS 0.08f
#define MAX_ROUGHNESS 0.5f
#define N_MIPS 6

// Paired array holds mips 1..5 only (mip0 sampled raw from the input buffer).
#define PAIR_TOTAL_TEXELS 523776
#define DIFF_TEXELS 1536
#define FG_TEXELS 65536

__constant__ int PAIR_OFF[6] = {0, 393216, 491520, 516096, 522240, 523776};

__device__ uint4  g_spec[PAIR_TOTAL_TEXELS];  // fp16 rgb|rgb pairs (8.4 MB)
__device__ uint4  g_diff[DIFF_TEXELS];        // fp16 rgb|rgb pairs (24 KB)
__device__ float4 g_fg[FG_TEXELS];            // fp32 (fg0,fg1)|(fg0,fg1) (1 MB)

struct SpecTable {
    const float* p[N_MIPS];
};

struct float3x { float x, y, z; };

// ---------------------------------------------------------------------------
// Repack pass (mips 1..5 + diffuse + fg; ~16 MB traffic)
// ---------------------------------------------------------------------------
__device__ __forceinline__ uint4 pack_pair(float lr, float lg, float lb,
                                           float hr, float hg, float hb) {
    __half2 A = __floats2half2_rn(lr, lg);
    __half2 B = __floats2half2_rn(lb, hr);
    __half2 C = __floats2half2_rn(hg, hb);
    uint4 o;
    o.x = *reinterpret_cast<unsigned int*>(&A);
    o.y = *reinterpret_cast<unsigned int*>(&B);
    o.z = *reinterpret_cast<unsigned int*>(&C);
    o.w = 0u;
    return o;
}

__device__ __forceinline__ void repack_rgb_chunk(const float* __restrict__ in,
                                                 uint4* __restrict__ out,
                                                 int local, int R) {
    int x = local % R;
    const float4* p = (const float4*)(in + (size_t)local * 3);
    float4 a = __ldg(p + 0);
    float4 b = __ldg(p + 1);
    float4 c = __ldg(p + 2);
    float f[16];
    f[0] = a.x; f[1] = a.y; f[2]  = a.z; f[3]  = a.w;
    f[4] = b.x; f[5] = b.y; f[6]  = b.z; f[7]  = b.w;
    f[8] = c.x; f[9] = c.y; f[10] = c.z; f[11] = c.w;
    bool has_next = (x + 4 < R);
    if (has_next) {
        float4 d = __ldg(p + 3);
        f[12] = d.x; f[13] = d.y; f[14] = d.z; f[15] = d.w;
    } else {
        f[12] = f[9]; f[13] = f[10]; f[14] = f[11]; f[15] = 0.0f;
    }
    #pragma unroll
    for (int i = 0; i < 4; i++) {
        out[local + i] = pack_pair(f[3 * i + 0], f[3 * i + 1], f[3 * i + 2],
                                   f[3 * i + 3], f[3 * i + 4], f[3 * i + 5]);
    }
}

__global__ void __launch_bounds__(256)
repack_kernel(SpecTable specs, const float* __restrict__ diffuse,
              const float* __restrict__ fg_lut) {
    const int QS = PAIR_TOTAL_TEXELS / 4;
    const int QD = QS + DIFF_TEXELS / 4;
    const int QF = QD + FG_TEXELS / 4;
    int q = blockIdx.x * blockDim.x + threadIdx.x;
    if (q >= QF) return;

    if (q < QS) {
        int t = q * 4;
        int lvl = 1;
        if (t >= 393216) lvl = 2;
        if (t >= 491520) lvl = 3;
        if (t >= 516096) lvl = 4;
        if (t >= 522240) lvl = 5;
        int local = t - PAIR_OFF[lvl - 1];
        repack_rgb_chunk(specs.p[lvl], g_spec + PAIR_OFF[lvl - 1], local, 512 >> lvl);
    } else if (q < QD) {
        int local = (q - QS) * 4;
        repack_rgb_chunk(diffuse, g_diff, local, 16);
    } else {
        int t = (q - QD) * 4;
        int x = t % 256;
        const float4* p = (const float4*)(fg_lut + (size_t)t * 2);
        float4 a = __ldg(p + 0);
        float4 b = __ldg(p + 1);
        float f[12];
        f[0] = a.x; f[1] = a.y; f[2] = a.z; f[3] = a.w;
        f[4] = b.x; f[5] = b.y; f[6] = b.z; f[7] = b.w;
        bool has_next = (x + 4 < 256);
        if (has_next) {
            float4 c = __ldg(p + 2);
            f[8] = c.x; f[9] = c.y; f[10] = c.z; f[11] = c.w;
        } else {
            f[8] = f[6]; f[9] = f[7]; f[10] = 0.0f; f[11] = 0.0f;
        }
        #pragma unroll
        for (int i = 0; i < 4; i++) {
            g_fg[t + i] = make_float4(f[2 * i + 0], f[2 * i + 1],
                                      f[2 * i + 2], f[2 * i + 3]);
        }
    }
}

// ---------------------------------------------------------------------------
// Main shading kernel
// ---------------------------------------------------------------------------
__device__ __forceinline__ void cube_face_uv(float x, float y, float z,
                                             int& face, float& u, float& v) {
    float ax = fabsf(x), ay = fabsf(y), az = fabsf(z);
    bool is_x = (ax >= ay) && (ax >= az);
    bool is_y = (!is_x) && (ay >= az);
    face = is_x ? (x >= 0.0f ? 0 : 1)
                : (is_y ? (y >= 0.0f ? 2 : 3)
                        : (z >= 0.0f ? 4 : 5));
    float ma = fmaxf(is_x ? ax : (is_y ? ay : az), 1e-20f);
    float un = (face == 0) ? -z : (face == 1) ? z : (face == 5) ? -x : x;
    float vn = (face == 2) ? z : (face == 3) ? -z : -y;
    float inv = __fdividef(1.0f, ma);
    u = un * inv;
    v = vn * inv;
}

__device__ __forceinline__ void pair_setup(float Rf, float tu, float tv,
                                           int& x0, int& y0, int& y1,
                                           float& fx, float& fy) {
    float x0f = floorf(tu);
    float y0f = floorf(tv);
    fx = tu - x0f;
    if (x0f < 0.0f) fx = 0.0f;
    fy = tv - y0f;
    x0 = (int)fminf(fmaxf(x0f, 0.0f), Rf - 1.0f);
    y0 = (int)fminf(fmaxf(y0f, 0.0f), Rf - 1.0f);
    y1 = (int)fminf(fmaxf(y0f + 1.0f, 0.0f), Rf - 1.0f);
}

__device__ __forceinline__ float3x pair_lerp(uint4 e0, uint4 e1, float fx, float fy) {
    float2 A0 = __half22float2(*reinterpret_cast<const __half2*>(&e0.x));
    float2 B0 = __half22float2(*reinterpret_cast<const __half2*>(&e0.y));
    float2 C0 = __half22float2(*reinterpret_cast<const __half2*>(&e0.z));
    float2 A1 = __half22float2(*reinterpret_cast<const __half2*>(&e1.x));
    float2 B1 = __half22float2(*reinterpret_cast<const __half2*>(&e1.y));
    float2 C1 = __half22float2(*reinterpret_cast<const __half2*>(&e1.z));

    float r0 = A0.x + fx * (B0.y - A0.x);
    float g0 = A0.y + fx * (C0.x - A0.y);
    float b0 = B0.x + fx * (C0.y - B0.x);
    float r1 = A1.x + fx * (B1.y - A1.x);
    float g1 = A1.y + fx * (C1.x - A1.y);
    float b1 = B1.x + fx * (C1.y - B1.x);

    float3x r;
    r.x = r0 + fy * (r1 - r0);
    r.y = g0 + fy * (g1 - g0);
    r.z = b0 + fy * (b1 - b0);
    return r;
}

__device__ __forceinline__ float3x cube_bilinear_pair(const uint4* __restrict__ tex,
                                                      int R, int face,
                                                      float u, float v) {
    float Rf = (float)R;
    float tu = fmaf(u, 0.5f * Rf, 0.5f * Rf - 0.5f);
    float tv = fmaf(v, 0.5f * Rf, 0.5f * Rf - 0.5f);
    int x0, y0, y1; float fx, fy;
    pair_setup(Rf, tu, tv, x0, y0, y1, fx, fy);
    int base = face * R * R + x0;
    uint4 e0 = __ldg(tex + base + y0 * R);
    uint4 e1 = __ldg(tex + base + y1 * R);
    return pair_lerp(e0, e1, fx, fy);
}

// Diffuse sample from the smem-cached paired cube (16^2 faces).
__device__ __forceinline__ float3x cube_bilinear_smem(const uint4* s_diff,
                                                      int face, float u, float v) {
    const float Rf = 16.0f;
    float tu = fmaf(u, 8.0f, 7.5f);
    float tv = fmaf(v, 8.0f, 7.5f);
    int x0, y0, y1; float fx, fy;
    pair_setup(Rf, tu, tv, x0, y0, y1, fx, fy);
    int base = face * 256 + x0;
    uint4 e0 = s_diff[base + y0 * 16];
    uint4 e1 = s_diff[base + y1 * 16];
    return pair_lerp(e0, e1, fx, fy);
}

// Raw fp32 RGB bilinear on the original mip-0 buffer (exact).
__device__ __forceinline__ float3x cube_bilinear_raw(const float* __restrict__ tex,
                                                     int face, float u, float v) {
    const float Rf = 512.0f;
    float tu = fmaf(u, 0.5f * Rf, 0.5f * Rf - 0.5f);
    float tv = fmaf(v, 0.5f * Rf, 0.5f * Rf - 0.5f);
    float x0f = floorf(tu);
    float y0f = floorf(tv);
    float fx = tu - x0f;
    float fy = tv - y0f;
    int x0 = (int)fminf(fmaxf(x0f, 0.0f), Rf - 1.0f);
    int x1 = (int)fminf(fmaxf(x0f + 1.0f, 0.0f), Rf - 1.0f);
    int y0 = (int)fminf(fmaxf(y0f, 0.0f), Rf - 1.0f);
    int y1 = (int)fminf(fmaxf(y0f + 1.0f, 0.0f), Rf - 1.0f);

    int baseF = face * 512 * 512;
    int i00 = (baseF + y0 * 512 + x0) * 3;
    int i01 = (baseF + y0 * 512 + x1) * 3;
    int i10 = (baseF + y1 * 512 + x0) * 3;
    int i11 = (baseF + y1 * 512 + x1) * 3;

    float w00 = (1.0f - fx) * (1.0f - fy);
    float w01 = fx * (1.0f - fy);
    float w10 = (1.0f - fx) * fy;
    float w11 = fx * fy;

    float3x r;
    r.x = __ldg(tex + i00 + 0) * w00 + __ldg(tex + i01 + 0) * w01 +
          __ldg(tex + i10 + 0) * w10 + __ldg(tex + i11 + 0) * w11;
    r.y = __ldg(tex + i00 + 1) * w00 + __ldg(tex + i01 + 1) * w01 +
          __ldg(tex + i10 + 1) * w10 + __ldg(tex + i11 + 1) * w11;
    r.z = __ldg(tex + i00 + 2) * w00 + __ldg(tex + i01 + 2) * w01 +
          __ldg(tex + i10 + 2) * w10 + __ldg(tex + i11 + 2) * w11;
    return r;
}

__device__ __forceinline__ float linear2srgb(float x) {
    float l = __log2f(x);
    float y = l * (1.0f / 2.4f);
    float fl = floorf(y);
    float t = y - fl;
    float p = fmaf(t,
              fmaf(t,
              fmaf(t,
              fmaf(t,
              fmaf(t, 0.0013333558f, 0.0096181291f),
                       0.0555041087f),
                       0.2402265070f),
                       0.6931471806f),
                       1.0f);
    int e = (int)fl;
    float r = __int_as_float(__float_as_int(p) + (e << 23));
    float hi = fmaf(1.055f, r, -0.055f);
    return (x > 0.0031308f) ? hi : 12.92f * x;
}

__global__ void __launch_bounds__(256, 5)
envlight_kernel(const float* __restrict__ gb_pos,
                const float* __restrict__ gb_normal,
                const float* __restrict__ basecolor,
                const float* __restrict__ metallic,
                const float* __restrict__ roughness,
                const float* __restrict__ view_pos,
                const float* __restrict__ spec0,
                float* __restrict__ out,
                int n) {
    __shared__ uint4 s_diff[DIFF_TEXELS];   // 24 KB

    // Fill smem diffuse cache (coalesced, 6 uint4 per thread).
    for (int k = threadIdx.x; k < DIFF_TEXELS; k += 256) {
        s_diff[k] = g_diff[k];
    }
    __syncthreads();

    float vx = __ldg(view_pos + 0);
    float vy = __ldg(view_pos + 1);
    float vz = __ldg(view_pos + 2);

    int stride = gridDim.x * blockDim.x;
    for (int i = blockIdx.x * blockDim.x + threadIdx.x; i < n; i += stride) {
        float px = gb_pos[i * 3 + 0];
        float py = gb_pos[i * 3 + 1];
        float pz = gb_pos[i * 3 + 2];
        float nx = gb_normal[i * 3 + 0];
        float ny = gb_normal[i * 3 + 1];
        float nz = gb_normal[i * 3 + 2];
        float bcx = basecolor[i * 3 + 0];
        float bcy = basecolor[i * 3 + 1];
        float bcz = basecolor[i * 3 + 2];
        float met = metallic[i];
        float rough = roughness[i];

        // wo left unnormalized; only NdotV needs the normalization factor.
        float wx = vx - px, wy = vy - py, wz = vz - pz;
        float wlen2 = fmaxf(wx * wx + wy * wy + wz * wz, 1e-20f);
        float winv = rsqrtf(wlen2);

        float om = 1.0f - met;
        float dax = om * bcx, day = om * bcy, daz = om * bcz;
        float sax = 0.04f * om + met * bcx;
        float say = 0.04f * om + met * bcy;
        float saz = 0.04f * om + met * bcz;

        float d_un = wx * nx + wy * ny + wz * nz;
        float rx = 2.0f * d_un * nx - wx;
        float ry = 2.0f * d_un * ny - wy;
        float rz = 2.0f * d_un * nz - wz;

        // ambient from diffuse cubemap (smem)
        int dface; float du, dv;
        cube_face_uv(nx, ny, nz, dface, du, dv);
        float3x ambient = cube_bilinear_smem(s_diff, dface, du, dv);

        float dlx = ambient.x * dax;
        float dly = ambient.y * day;
        float dlz = ambient.z * daz;

        // FG LUT (256x256x2, clamp, fp32 pairs)
        float NdotV = fmaxf(d_un * winv, 0.0001f);
        float fg0, fg1;
        {
            float tu = NdotV * 256.0f - 0.5f;
            float tv = rough * 256.0f - 0.5f;
            int x0, y0, y1; float fx, fy;
            pair_setup(256.0f, tu, tv, x0, y0, y1, fx, fy);
            float4 e0 = __ldg(g_fg + y0 * 256 + x0);
            float4 e1 = __ldg(g_fg + y1 * 256 + x0);
            float a0 = e0.x + fx * (e0.z - e0.x);
            float b0 = e0.y + fx * (e0.w - e0.y);
            float a1 = e1.x + fx * (e1.z - e1.x);
            float b1 = e1.y + fx * (e1.w - e1.y);
            fg0 = a0 + fy * (a1 - a0);
            fg1 = b0 + fy * (b1 - b0);
        }

        // mip
        float mip;
        {
            const float L = (float)N_MIPS;
            float lo = (fminf(fmaxf(rough, MIN_ROUGHNESS), MAX_ROUGHNESS) - MIN_ROUGHNESS)
                       * ((L - 2.0f) / (MAX_ROUGHNESS - MIN_ROUGHNESS));
            float hi = (fminf(fmaxf(rough, MAX_ROUGHNESS), 1.0f) - MAX_ROUGHNESS)
                       * (1.0f / (1.0f - MAX_ROUGHNESS)) + (L - 2.0f);
            mip = (rough < MAX_ROUGHNESS) ? lo : hi;
            mip = fminf(fmaxf(mip, 0.0f), L - 1.0f);
        }

        int sface; float su, sv;
        cube_face_uv(rx, ry, rz, sface, su, sv);

        int l0 = (int)floorf(mip);
        if (l0 > N_MIPS - 1) l0 = N_MIPS - 1;
        float f = mip - (float)l0;
        int l1 = l0 + 1;
        if (l1 > N_MIPS - 1) l1 = N_MIPS - 1;

        float3x s1 = cube_bilinear_pair(g_spec + PAIR_OFF[l1 - 1], 512 >> l1,
                                        sface, su, sv);
        float3x s0;
        if (l0 == 0) {
            s0 = cube_bilinear_raw(spec0, sface, su, sv);
        } else {
            s0 = cube_bilinear_pair(g_spec + PAIR_OFF[l0 - 1], 512 >> l0,
                                    sface, su, sv);
        }

        float spx = s0.x + f * (s1.x - s0.x);
        float spy = s0.y + f * (s1.y - s0.y);
        float spz = s0.z + f * (s1.z - s0.z);

        float refx = sax * fg0 + fg1;
        float refy = say * fg0 + fg1;
        float refz = saz * fg0 + fg1;

        float cx = fminf(fmaxf(spx * refx + dlx, 0.0f), 1.0f);
        float cy = fminf(fmaxf(spy * refy + dly, 0.0f), 1.0f);
        float cz = fminf(fmaxf(spz * refz + dlz, 0.0f), 1.0f);

        out[i * 3 + 0] = linear2srgb(cx);
        out[i * 3 + 1] = linear2srgb(cy);
        out[i * 3 + 2] = linear2srgb(cz);
    }
}

extern "C" void kernel_launch(void* const* d_in, const int* in_sizes, int n_in,
                              void* d_out, int out_size) {
    const float* gb_pos    = (const float*)d_in[0];
    const float* gb_normal = (const float*)d_in[1];
    const float* basecolor = (const float*)d_in[2];
    const float* metallic  = (const float*)d_in[3];
    const float* roughness = (const float*)d_in[4];
    const float* view_pos  = (const float*)d_in[5];
    const float* diffuse   = (const float*)d_in[6];
    const float* fg_lut    = (const float*)d_in[7];

    SpecTable specs;
    specs.p[0] = (const float*)d_in[8];
    specs.p[1] = (const float*)d_in[9];
    specs.p[2] = (const float*)d_in[10];
    specs.p[3] = (const float*)d_in[11];
    specs.p[4] = (const float*)d_in[12];
    specs.p[5] = (const float*)d_in[13];

    float* out = (float*)d_out;
    int n = in_sizes[0] / 3;

    // Pass 1: repack mips 1..5 + diffuse + fg
    {
        int chunks = PAIR_TOTAL_TEXELS / 4 + DIFF_TEXELS / 4 + FG_TEXELS / 4;
        int threads = 256;
        int blocks = (chunks + threads - 1) / threads;
        repack_kernel<<<blocks, threads>>>(specs, diffuse, fg_lut);
    }

    // Pass 2: shade, grid-stride persistent blocks (~5/SM)
    {
        int threads = 256;
        int blocks = 760;  // ~5 per SM on 152-SM GB300
        int max_blocks = (n + threads - 1) / threads;
        if (blocks > max_blocks) blocks = max_blocks;
        envlight_kernel<<<blocks, threads>>>(gb_pos, gb_normal, basecolor, metallic,
                                             roughness, view_pos, specs.p[0], out, n);
    }
}

// round 10
// speedup vs baseline: 1.1954x; 1.1954x over previous
#include <cuda_runtime.h>
#include <cuda_fp16.h>
#include <math.h>

#define MIN_ROUGHNESS 0.08f
#define MAX_ROUGHNESS 0.5f
#define N_MIPS 6

// Paired array holds mips 1..5 only (mip0 sampled raw from the input buffer).
#define PAIR_TOTAL_TEXELS 523776
#define DIFF_TEXELS 1536
#define FG_TEXELS 65536

__constant__ int PAIR_OFF[6] = {0, 393216, 491520, 516096, 522240, 523776};

__device__ uint4  g_spec[PAIR_TOTAL_TEXELS];  // fp16 rgb|rgb pairs (8.4 MB)
__device__ uint4  g_diff[DIFF_TEXELS];        // fp16 rgb|rgb pairs (24 KB)
__device__ float4 g_fg[FG_TEXELS];            // fp32 (fg0,fg1)|(fg0,fg1) (1 MB)

struct SpecTable {
    const float* p[N_MIPS];
};

struct float3x { float x, y, z; };

// ---------------------------------------------------------------------------
// Repack pass (mips 1..5 + diffuse + fg; ~16 MB traffic)
// ---------------------------------------------------------------------------
__device__ __forceinline__ uint4 pack_pair(float lr, float lg, float lb,
                                           float hr, float hg, float hb) {
    __half2 A = __floats2half2_rn(lr, lg);
    __half2 B = __floats2half2_rn(lb, hr);
    __half2 C = __floats2half2_rn(hg, hb);
    uint4 o;
    o.x = *reinterpret_cast<unsigned int*>(&A);
    o.y = *reinterpret_cast<unsigned int*>(&B);
    o.z = *reinterpret_cast<unsigned int*>(&C);
    o.w = 0u;
    return o;
}

__device__ __forceinline__ void repack_rgb_chunk(const float* __restrict__ in,
                                                 uint4* __restrict__ out,
                                                 int local, int R) {
    int x = local % R;
    const float4* p = (const float4*)(in + (size_t)local * 3);
    float4 a = __ldg(p + 0);
    float4 b = __ldg(p + 1);
    float4 c = __ldg(p + 2);
    float f[16];
    f[0] = a.x; f[1] = a.y; f[2]  = a.z; f[3]  = a.w;
    f[4] = b.x; f[5] = b.y; f[6]  = b.z; f[7]  = b.w;
    f[8] = c.x; f[9] = c.y; f[10] = c.z; f[11] = c.w;
    bool has_next = (x + 4 < R);
    if (has_next) {
        float4 d = __ldg(p + 3);
        f[12] = d.x; f[13] = d.y; f[14] = d.z; f[15] = d.w;
    } else {
        f[12] = f[9]; f[13] = f[10]; f[14] = f[11]; f[15] = 0.0f;
    }
    #pragma unroll
    for (int i = 0; i < 4; i++) {
        out[local + i] = pack_pair(f[3 * i + 0], f[3 * i + 1], f[3 * i + 2],
                                   f[3 * i + 3], f[3 * i + 4], f[3 * i + 5]);
    }
}

__global__ void __launch_bounds__(256)
repack_kernel(SpecTable specs, const float* __restrict__ diffuse,
              const float* __restrict__ fg_lut) {
    const int QS = PAIR_TOTAL_TEXELS / 4;
    const int QD = QS + DIFF_TEXELS / 4;
    const int QF = QD + FG_TEXELS / 4;
    int q = blockIdx.x * blockDim.x + threadIdx.x;
    if (q >= QF) return;

    if (q < QS) {
        int t = q * 4;
        int lvl = 1;
        if (t >= 393216) lvl = 2;
        if (t >= 491520) lvl = 3;
        if (t >= 516096) lvl = 4;
        if (t >= 522240) lvl = 5;
        int local = t - PAIR_OFF[lvl - 1];
        repack_rgb_chunk(specs.p[lvl], g_spec + PAIR_OFF[lvl - 1], local, 512 >> lvl);
    } else if (q < QD) {
        int local = (q - QS) * 4;
        repack_rgb_chunk(diffuse, g_diff, local, 16);
    } else {
        int t = (q - QD) * 4;
        int x = t % 256;
        const float4* p = (const float4*)(fg_lut + (size_t)t * 2);
        float4 a = __ldg(p + 0);
        float4 b = __ldg(p + 1);
        float f[12];
        f[0] = a.x; f[1] = a.y; f[2] = a.z; f[3] = a.w;
        f[4] = b.x; f[5] = b.y; f[6] = b.z; f[7] = b.w;
        bool has_next = (x + 4 < 256);
        if (has_next) {
            float4 c = __ldg(p + 2);
            f[8] = c.x; f[9] = c.y; f[10] = c.z; f[11] = c.w;
        } else {
            f[8] = f[6]; f[9] = f[7]; f[10] = 0.0f; f[11] = 0.0f;
        }
        #pragma unroll
        for (int i = 0; i < 4; i++) {
            g_fg[t + i] = make_float4(f[2 * i + 0], f[2 * i + 1],
                                      f[2 * i + 2], f[2 * i + 3]);
        }
    }
}

// ---------------------------------------------------------------------------
// Main shading kernel
// ---------------------------------------------------------------------------
__device__ __forceinline__ void cube_face_uv(float x, float y, float z,
                                             int& face, float& u, float& v) {
    float ax = fabsf(x), ay = fabsf(y), az = fabsf(z);
    bool is_x = (ax >= ay) && (ax >= az);
    bool is_y = (!is_x) && (ay >= az);
    face = is_x ? (x >= 0.0f ? 0 : 1)
                : (is_y ? (y >= 0.0f ? 2 : 3)
                        : (z >= 0.0f ? 4 : 5));
    float ma = fmaxf(is_x ? ax : (is_y ? ay : az), 1e-20f);
    float un = (face == 0) ? -z : (face == 1) ? z : (face == 5) ? -x : x;
    float vn = (face == 2) ? z : (face == 3) ? -z : -y;
    float inv = __fdividef(1.0f, ma);
    u = un * inv;
    v = vn * inv;
}

__device__ __forceinline__ void pair_setup(float Rf, float tu, float tv,
                                           int& x0, int& y0, int& y1,
                                           float& fx, float& fy) {
    float x0f = floorf(tu);
    float y0f = floorf(tv);
    fx = tu - x0f;
    if (x0f < 0.0f) fx = 0.0f;
    fy = tv - y0f;
    x0 = (int)fminf(fmaxf(x0f, 0.0f), Rf - 1.0f);
    y0 = (int)fminf(fmaxf(y0f, 0.0f), Rf - 1.0f);
    y1 = (int)fminf(fmaxf(y0f + 1.0f, 0.0f), Rf - 1.0f);
}

__device__ __forceinline__ float3x pair_lerp(uint4 e0, uint4 e1, float fx, float fy) {
    float2 A0 = __half22float2(*reinterpret_cast<const __half2*>(&e0.x));
    float2 B0 = __half22float2(*reinterpret_cast<const __half2*>(&e0.y));
    float2 C0 = __half22float2(*reinterpret_cast<const __half2*>(&e0.z));
    float2 A1 = __half22float2(*reinterpret_cast<const __half2*>(&e1.x));
    float2 B1 = __half22float2(*reinterpret_cast<const __half2*>(&e1.y));
    float2 C1 = __half22float2(*reinterpret_cast<const __half2*>(&e1.z));

    float r0 = A0.x + fx * (B0.y - A0.x);
    float g0 = A0.y + fx * (C0.x - A0.y);
    float b0 = B0.x + fx * (C0.y - B0.x);
    float r1 = A1.x + fx * (B1.y - A1.x);
    float g1 = A1.y + fx * (C1.x - A1.y);
    float b1 = B1.x + fx * (C1.y - B1.x);

    float3x r;
    r.x = r0 + fy * (r1 - r0);
    r.y = g0 + fy * (g1 - g0);
    r.z = b0 + fy * (b1 - b0);
    return r;
}

__device__ __forceinline__ float3x cube_bilinear_pair(const uint4* __restrict__ tex,
                                                      int R, int face,
                                                      float u, float v) {
    float Rf = (float)R;
    float tu = fmaf(u, 0.5f * Rf, 0.5f * Rf - 0.5f);
    float tv = fmaf(v, 0.5f * Rf, 0.5f * Rf - 0.5f);
    int x0, y0, y1; float fx, fy;
    pair_setup(Rf, tu, tv, x0, y0, y1, fx, fy);
    int base = face * R * R + x0;
    uint4 e0 = __ldg(tex + base + y0 * R);
    uint4 e1 = __ldg(tex + base + y1 * R);
    return pair_lerp(e0, e1, fx, fy);
}

// Raw fp32 RGB bilinear on the original mip-0 buffer (exact).
__device__ __forceinline__ float3x cube_bilinear_raw(const float* __restrict__ tex,
                                                     int face, float u, float v) {
    const float Rf = 512.0f;
    float tu = fmaf(u, 0.5f * Rf, 0.5f * Rf - 0.5f);
    float tv = fmaf(v, 0.5f * Rf, 0.5f * Rf - 0.5f);
    float x0f = floorf(tu);
    float y0f = floorf(tv);
    float fx = tu - x0f;
    float fy = tv - y0f;
    int x0 = (int)fminf(fmaxf(x0f, 0.0f), Rf - 1.0f);
    int x1 = (int)fminf(fmaxf(x0f + 1.0f, 0.0f), Rf - 1.0f);
    int y0 = (int)fminf(fmaxf(y0f, 0.0f), Rf - 1.0f);
    int y1 = (int)fminf(fmaxf(y0f + 1.0f, 0.0f), Rf - 1.0f);

    int baseF = face * 512 * 512;
    int i00 = (baseF + y0 * 512 + x0) * 3;
    int i01 = (baseF + y0 * 512 + x1) * 3;
    int i10 = (baseF + y1 * 512 + x0) * 3;
    int i11 = (baseF + y1 * 512 + x1) * 3;

    float w00 = (1.0f - fx) * (1.0f - fy);
    float w01 = fx * (1.0f - fy);
    float w10 = (1.0f - fx) * fy;
    float w11 = fx * fy;

    float3x r;
    r.x = __ldg(tex + i00 + 0) * w00 + __ldg(tex + i01 + 0) * w01 +
          __ldg(tex + i10 + 0) * w10 + __ldg(tex + i11 + 0) * w11;
    r.y = __ldg(tex + i00 + 1) * w00 + __ldg(tex + i01 + 1) * w01 +
          __ldg(tex + i10 + 1) * w10 + __ldg(tex + i11 + 1) * w11;
    r.z = __ldg(tex + i00 + 2) * w00 + __ldg(tex + i01 + 2) * w01 +
          __ldg(tex + i10 + 2) * w10 + __ldg(tex + i11 + 2) * w11;
    return r;
}

__device__ __forceinline__ float linear2srgb(float x) {
    float l = __log2f(x);
    float y = l * (1.0f / 2.4f);
    float fl = floorf(y);
    float t = y - fl;
    float p = fmaf(t,
              fmaf(t,
              fmaf(t,
              fmaf(t,
              fmaf(t, 0.0013333558f, 0.0096181291f),
                       0.0555041087f),
                       0.2402265070f),
                       0.6931471806f),
                       1.0f);
    int e = (int)fl;
    float r = __int_as_float(__float_as_int(p) + (e << 23));
    float hi = fmaf(1.055f, r, -0.055f);
    return (x > 0.0031308f) ? hi : 12.92f * x;
}

__global__ void __launch_bounds__(256, 6)
envlight_kernel1(const float* __restrict__ gb_pos,
                 const float* __restrict__ gb_normal,
                 const float* __restrict__ basecolor,
                 const float* __restrict__ metallic,
                 const float* __restrict__ roughness,
                 const float* __restrict__ view_pos,
                 const float* __restrict__ spec0,
                 float* __restrict__ out,
                 int n) {
    int i = blockIdx.x * blockDim.x + threadIdx.x;
    if (i >= n) return;

    float vx = __ldg(view_pos + 0);
    float vy = __ldg(view_pos + 1);
    float vz = __ldg(view_pos + 2);

    // Read-once streaming loads: evict-first so texel lines stay cached.
    float px = __ldcs(gb_pos + i * 3 + 0);
    float py = __ldcs(gb_pos + i * 3 + 1);
    float pz = __ldcs(gb_pos + i * 3 + 2);
    float nx = __ldcs(gb_normal + i * 3 + 0);
    float ny = __ldcs(gb_normal + i * 3 + 1);
    float nz = __ldcs(gb_normal + i * 3 + 2);
    float bcx = __ldcs(basecolor + i * 3 + 0);
    float bcy = __ldcs(basecolor + i * 3 + 1);
    float bcz = __ldcs(basecolor + i * 3 + 2);
    float met = __ldcs(metallic + i);
    float rough = __ldcs(roughness + i);

    // wo left unnormalized; only NdotV needs the normalization factor.
    float wx = vx - px, wy = vy - py, wz = vz - pz;
    float wlen2 = fmaxf(wx * wx + wy * wy + wz * wz, 1e-20f);
    float winv = rsqrtf(wlen2);

    float om = 1.0f - met;
    float dax = om * bcx, day = om * bcy, daz = om * bcz;
    float sax = 0.04f * om + met * bcx;
    float say = 0.04f * om + met * bcy;
    float saz = 0.04f * om + met * bcz;

    float d_un = wx * nx + wy * ny + wz * nz;
    float rx = 2.0f * d_un * nx - wx;
    float ry = 2.0f * d_un * ny - wy;
    float rz = 2.0f * d_un * nz - wz;

    // ambient from diffuse cubemap (16^2, fp16 pairs)
    int dface; float du, dv;
    cube_face_uv(nx, ny, nz, dface, du, dv);
    float3x ambient = cube_bilinear_pair(g_diff, 16, dface, du, dv);

    float dlx = ambient.x * dax;
    float dly = ambient.y * day;
    float dlz = ambient.z * daz;

    // FG LUT (256x256x2, clamp, fp32 pairs)
    float NdotV = fmaxf(d_un * winv, 0.0001f);
    float fg0, fg1;
    {
        float tu = NdotV * 256.0f - 0.5f;
        float tv = rough * 256.0f - 0.5f;
        int x0, y0, y1; float fx, fy;
        pair_setup(256.0f, tu, tv, x0, y0, y1, fx, fy);
        float4 e0 = __ldg(g_fg + y0 * 256 + x0);
        float4 e1 = __ldg(g_fg + y1 * 256 + x0);
        float a0 = e0.x + fx * (e0.z - e0.x);
        float b0 = e0.y + fx * (e0.w - e0.y);
        float a1 = e1.x + fx * (e1.z - e1.x);
        float b1 = e1.y + fx * (e1.w - e1.y);
        fg0 = a0 + fy * (a1 - a0);
        fg1 = b0 + fy * (b1 - b0);
    }

    // mip
    float mip;
    {
        const float L = (float)N_MIPS;
        float lo = (fminf(fmaxf(rough, MIN_ROUGHNESS), MAX_ROUGHNESS) - MIN_ROUGHNESS)
                   * ((L - 2.0f) / (MAX_ROUGHNESS - MIN_ROUGHNESS));
        float hi = (fminf(fmaxf(rough, MAX_ROUGHNESS), 1.0f) - MAX_ROUGHNESS)
                   * (1.0f / (1.0f - MAX_ROUGHNESS)) + (L - 2.0f);
        mip = (rough < MAX_ROUGHNESS) ? lo : hi;
        mip = fminf(fmaxf(mip, 0.0f), L - 1.0f);
    }

    int sface; float su, sv;
    cube_face_uv(rx, ry, rz, sface, su, sv);

    int l0 = (int)floorf(mip);
    if (l0 > N_MIPS - 1) l0 = N_MIPS - 1;
    float f = mip - (float)l0;
    int l1 = l0 + 1;
    if (l1 > N_MIPS - 1) l1 = N_MIPS - 1;   // f==0 there

    // s1 always lives in the paired array (l1 >= 1 always).
    float3x s1 = cube_bilinear_pair(g_spec + PAIR_OFF[l1 - 1], 512 >> l1,
                                    sface, su, sv);
    // s0: raw fp32 mip0 if l0==0 (~18.5% of pixels), else paired.
    float3x s0;
    if (l0 == 0) {
        s0 = cube_bilinear_raw(spec0, sface, su, sv);
    } else {
        s0 = cube_bilinear_pair(g_spec + PAIR_OFF[l0 - 1], 512 >> l0,
                                sface, su, sv);
    }

    float spx = s0.x + f * (s1.x - s0.x);
    float spy = s0.y + f * (s1.y - s0.y);
    float spz = s0.z + f * (s1.z - s0.z);

    float refx = sax * fg0 + fg1;
    float refy = say * fg0 + fg1;
    float refz = saz * fg0 + fg1;

    float cx = fminf(fmaxf(spx * refx + dlx, 0.0f), 1.0f);
    float cy = fminf(fmaxf(spy * refy + dly, 0.0f), 1.0f);
    float cz = fminf(fmaxf(spz * refz + dlz, 0.0f), 1.0f);

    // Write-once streaming stores.
    __stcs(out + i * 3 + 0, linear2srgb(cx));
    __stcs(out + i * 3 + 1, linear2srgb(cy));
    __stcs(out + i * 3 + 2, linear2srgb(cz));
}

extern "C" void kernel_launch(void* const* d_in, const int* in_sizes, int n_in,
                              void* d_out, int out_size) {
    const float* gb_pos    = (const float*)d_in[0];
    const float* gb_normal = (const float*)d_in[1];
    const float* basecolor = (const float*)d_in[2];
    const float* metallic  = (const float*)d_in[3];
    const float* roughness = (const float*)d_in[4];
    const float* view_pos  = (const float*)d_in[5];
    const float* diffuse   = (const float*)d_in[6];
    const float* fg_lut    = (const float*)d_in[7];

    SpecTable specs;
    specs.p[0] = (const float*)d_in[8];
    specs.p[1] = (const float*)d_in[9];
    specs.p[2] = (const float*)d_in[10];
    specs.p[3] = (const float*)d_in[11];
    specs.p[4] = (const float*)d_in[12];
    specs.p[5] = (const float*)d_in[13];

    float* out = (float*)d_out;
    int n = in_sizes[0] / 3;

    // Pass 1: repack mips 1..5 + diffuse + fg (mip0 stays raw)
    {
        int chunks = PAIR_TOTAL_TEXELS / 4 + DIFF_TEXELS / 4 + FG_TEXELS / 4;
        int threads = 256;
        int blocks = (chunks + threads - 1) / threads;
        repack_kernel<<<blocks, threads>>>(specs, diffuse, fg_lut);
    }

    // Pass 2: shade, 1 px/thread at 6 blocks/SM
    {
        int threads = 256;
        int blocks = (n + threads - 1) / threads;
        envlight_kernel1<<<blocks, threads>>>(gb_pos, gb_normal, basecolor, metallic,
                                              roughness, view_pos, specs.p[0], out, n);
    }
}

// round 11
// speedup vs baseline: 1.2636x; 1.0571x over previous
#include <cuda_runtime.h>
#include <cuda_fp16.h>
#include <math.h>

#define MIN_ROUGHNESS 0.08f
#define MAX_ROUGHNESS 0.5f
#define N_MIPS 6

// Paired array holds mips 1..5 only (mip0 sampled raw from the input buffer).
#define PAIR_TOTAL_TEXELS 523776
#define DIFF_TEXELS 1536
#define FG_TEXELS 65536

__constant__ int PAIR_OFF[6] = {0, 393216, 491520, 516096, 522240, 523776};

__device__ uint4 g_spec[PAIR_TOTAL_TEXELS];  // fp16 rgb|rgb pairs (8.4 MB)
__device__ uint4 g_diff[DIFF_TEXELS];        // fp16 rgb|rgb pairs (24 KB)
// FG quad record at (x,y): fp16 (fg0,fg1) at (x,y),(x+1,y),(x,y+1),(x+1,y+1)
__device__ uint4 g_fgq[FG_TEXELS];           // 1 MB

struct SpecTable {
    const float* p[N_MIPS];
};

struct float3x { float x, y, z; };

// ---------------------------------------------------------------------------
// Repack pass
// ---------------------------------------------------------------------------
__device__ __forceinline__ uint4 pack_pair(float lr, float lg, float lb,
                                           float hr, float hg, float hb) {
    __half2 A = __floats2half2_rn(lr, lg);
    __half2 B = __floats2half2_rn(lb, hr);
    __half2 C = __floats2half2_rn(hg, hb);
    uint4 o;
    o.x = *reinterpret_cast<unsigned int*>(&A);
    o.y = *reinterpret_cast<unsigned int*>(&B);
    o.z = *reinterpret_cast<unsigned int*>(&C);
    o.w = 0u;
    return o;
}

__device__ __forceinline__ void repack_rgb_chunk(const float* __restrict__ in,
                                                 uint4* __restrict__ out,
                                                 int local, int R) {
    int x = local % R;
    const float4* p = (const float4*)(in + (size_t)local * 3);
    float4 a = __ldg(p + 0);
    float4 b = __ldg(p + 1);
    float4 c = __ldg(p + 2);
    float f[16];
    f[0] = a.x; f[1] = a.y; f[2]  = a.z; f[3]  = a.w;
    f[4] = b.x; f[5] = b.y; f[6]  = b.z; f[7]  = b.w;
    f[8] = c.x; f[9] = c.y; f[10] = c.z; f[11] = c.w;
    bool has_next = (x + 4 < R);
    if (has_next) {
        float4 d = __ldg(p + 3);
        f[12] = d.x; f[13] = d.y; f[14] = d.z; f[15] = d.w;
    } else {
        f[12] = f[9]; f[13] = f[10]; f[14] = f[11]; f[15] = 0.0f;
    }
    #pragma unroll
    for (int i = 0; i < 4; i++) {
        out[local + i] = pack_pair(f[3 * i + 0], f[3 * i + 1], f[3 * i + 2],
                                   f[3 * i + 3], f[3 * i + 4], f[3 * i + 5]);
    }
}

__global__ void __launch_bounds__(256)
repack_kernel(SpecTable specs, const float* __restrict__ diffuse,
              const float* __restrict__ fg_lut) {
    const int QS = PAIR_TOTAL_TEXELS / 4;
    const int QD = QS + DIFF_TEXELS / 4;
    const int QF = QD + FG_TEXELS / 4;
    int q = blockIdx.x * blockDim.x + threadIdx.x;
    if (q >= QF) return;

    if (q < QS) {
        int t = q * 4;
        int lvl = 1;
        if (t >= 393216) lvl = 2;
        if (t >= 491520) lvl = 3;
        if (t >= 516096) lvl = 4;
        if (t >= 522240) lvl = 5;
        int local = t - PAIR_OFF[lvl - 1];
        repack_rgb_chunk(specs.p[lvl], g_spec + PAIR_OFF[lvl - 1], local, 512 >> lvl);
    } else if (q < QD) {
        int local = (q - QS) * 4;
        repack_rgb_chunk(diffuse, g_diff, local, 16);
    } else {
        // FG quad records: 4 records per thread (same row).
        int t = (q - QD) * 4;
        int y = t / 256;
        int x = t % 256;
        int y1 = (y + 1 < 256) ? (y + 1) : y;
        const float2* fg = (const float2*)fg_lut;
        #pragma unroll
        for (int i = 0; i < 4; i++) {
            int xi = x + i;
            int x1 = (xi + 1 < 256) ? (xi + 1) : xi;
            float2 c00 = __ldg(fg + y  * 256 + xi);
            float2 c01 = __ldg(fg + y  * 256 + x1);
            float2 c10 = __ldg(fg + y1 * 256 + xi);
            float2 c11 = __ldg(fg + y1 * 256 + x1);
            __half2 h00 = __floats2half2_rn(c00.x, c00.y);
            __half2 h01 = __floats2half2_rn(c01.x, c01.y);
            __half2 h10 = __floats2half2_rn(c10.x, c10.y);
            __half2 h11 = __floats2half2_rn(c11.x, c11.y);
            uint4 o;
            o.x = *reinterpret_cast<unsigned int*>(&h00);
            o.y = *reinterpret_cast<unsigned int*>(&h01);
            o.z = *reinterpret_cast<unsigned int*>(&h10);
            o.w = *reinterpret_cast<unsigned int*>(&h11);
            g_fgq[t + i] = o;
        }
    }
}

// ---------------------------------------------------------------------------
// Main shading kernel
// ---------------------------------------------------------------------------
__device__ __forceinline__ void cube_face_uv(float x, float y, float z,
                                             int& face, float& u, float& v) {
    float ax = fabsf(x), ay = fabsf(y), az = fabsf(z);
    bool is_x = (ax >= ay) && (ax >= az);
    bool is_y = (!is_x) && (ay >= az);
    face = is_x ? (x >= 0.0f ? 0 : 1)
                : (is_y ? (y >= 0.0f ? 2 : 3)
                        : (z >= 0.0f ? 4 : 5));
    float ma = fmaxf(is_x ? ax : (is_y ? ay : az), 1e-20f);
    float un = (face == 0) ? -z : (face == 1) ? z : (face == 5) ? -x : x;
    float vn = (face == 2) ? z : (face == 3) ? -z : -y;
    float inv = __fdividef(1.0f, ma);
    u = un * inv;
    v = vn * inv;
}

__device__ __forceinline__ void pair_setup(float Rf, float tu, float tv,
                                           int& x0, int& y0, int& y1,
                                           float& fx, float& fy) {
    float x0f = floorf(tu);
    float y0f = floorf(tv);
    fx = tu - x0f;
    if (x0f < 0.0f) fx = 0.0f;
    fy = tv - y0f;
    x0 = (int)fminf(fmaxf(x0f, 0.0f), Rf - 1.0f);
    y0 = (int)fminf(fmaxf(y0f, 0.0f), Rf - 1.0f);
    y1 = (int)fminf(fmaxf(y0f + 1.0f, 0.0f), Rf - 1.0f);
}

__device__ __forceinline__ float3x pair_lerp(uint4 e0, uint4 e1, float fx, float fy) {
    float2 A0 = __half22float2(*reinterpret_cast<const __half2*>(&e0.x));
    float2 B0 = __half22float2(*reinterpret_cast<const __half2*>(&e0.y));
    float2 C0 = __half22float2(*reinterpret_cast<const __half2*>(&e0.z));
    float2 A1 = __half22float2(*reinterpret_cast<const __half2*>(&e1.x));
    float2 B1 = __half22float2(*reinterpret_cast<const __half2*>(&e1.y));
    float2 C1 = __half22float2(*reinterpret_cast<const __half2*>(&e1.z));

    float r0 = A0.x + fx * (B0.y - A0.x);
    float g0 = A0.y + fx * (C0.x - A0.y);
    float b0 = B0.x + fx * (C0.y - B0.x);
    float r1 = A1.x + fx * (B1.y - A1.x);
    float g1 = A1.y + fx * (C1.x - A1.y);
    float b1 = B1.x + fx * (C1.y - B1.x);

    float3x r;
    r.x = r0 + fy * (r1 - r0);
    r.y = g0 + fy * (g1 - g0);
    r.z = b0 + fy * (b1 - b0);
    return r;
}

__device__ __forceinline__ float3x cube_bilinear_pair(const uint4* __restrict__ tex,
                                                      int R, int face,
                                                      float u, float v) {
    float Rf = (float)R;
    float tu = fmaf(u, 0.5f * Rf, 0.5f * Rf - 0.5f);
    float tv = fmaf(v, 0.5f * Rf, 0.5f * Rf - 0.5f);
    int x0, y0, y1; float fx, fy;
    pair_setup(Rf, tu, tv, x0, y0, y1, fx, fy);
    int base = face * R * R + x0;
    uint4 e0 = __ldg(tex + base + y0 * R);
    uint4 e1 = __ldg(tex + base + y1 * R);
    return pair_lerp(e0, e1, fx, fy);
}

// Raw fp32 RGB bilinear on the original mip-0 buffer (exact).
__device__ __forceinline__ float3x cube_bilinear_raw(const float* __restrict__ tex,
                                                     int face, float u, float v) {
    const float Rf = 512.0f;
    float tu = fmaf(u, 0.5f * Rf, 0.5f * Rf - 0.5f);
    float tv = fmaf(v, 0.5f * Rf, 0.5f * Rf - 0.5f);
    float x0f = floorf(tu);
    float y0f = floorf(tv);
    float fx = tu - x0f;
    float fy = tv - y0f;
    int x0 = (int)fminf(fmaxf(x0f, 0.0f), Rf - 1.0f);
    int x1 = (int)fminf(fmaxf(x0f + 1.0f, 0.0f), Rf - 1.0f);
    int y0 = (int)fminf(fmaxf(y0f, 0.0f), Rf - 1.0f);
    int y1 = (int)fminf(fmaxf(y0f + 1.0f, 0.0f), Rf - 1.0f);

    int baseF = face * 512 * 512;
    int i00 = (baseF + y0 * 512 + x0) * 3;
    int i01 = (baseF + y0 * 512 + x1) * 3;
    int i10 = (baseF + y1 * 512 + x0) * 3;
    int i11 = (baseF + y1 * 512 + x1) * 3;

    float w00 = (1.0f - fx) * (1.0f - fy);
    float w01 = fx * (1.0f - fy);
    float w10 = (1.0f - fx) * fy;
    float w11 = fx * fy;

    float3x r;
    r.x = __ldg(tex + i00 + 0) * w00 + __ldg(tex + i01 + 0) * w01 +
          __ldg(tex + i10 + 0) * w10 + __ldg(tex + i11 + 0) * w11;
    r.y = __ldg(tex + i00 + 1) * w00 + __ldg(tex + i01 + 1) * w01 +
          __ldg(tex + i10 + 1) * w10 + __ldg(tex + i11 + 1) * w11;
    r.z = __ldg(tex + i00 + 2) * w00 + __ldg(tex + i01 + 2) * w01 +
          __ldg(tex + i10 + 2) * w10 + __ldg(tex + i11 + 2) * w11;
    return r;
}

__device__ __forceinline__ float linear2srgb(float x) {
    float l = __log2f(x);
    float y = l * (1.0f / 2.4f);
    float fl = floorf(y);
    float t = y - fl;
    float p = fmaf(t,
              fmaf(t,
              fmaf(t,
              fmaf(t,
              fmaf(t, 0.0013333558f, 0.0096181291f),
                       0.0555041087f),
                       0.2402265070f),
                       0.6931471806f),
                       1.0f);
    int e = (int)fl;
    float r = __int_as_float(__float_as_int(p) + (e << 23));
    float hi = fmaf(1.055f, r, -0.055f);
    return (x > 0.0031308f) ? hi : 12.92f * x;
}

__global__ void __launch_bounds__(256, 6)
envlight_kernel1(const float* __restrict__ gb_pos,
                 const float* __restrict__ gb_normal,
                 const float* __restrict__ basecolor,
                 const float* __restrict__ metallic,
                 const float* __restrict__ roughness,
                 const float* __restrict__ view_pos,
                 const float* __restrict__ spec0,
                 float* __restrict__ out,
                 int n) {
    int i = blockIdx.x * blockDim.x + threadIdx.x;
    if (i >= n) return;

    float vx = __ldg(view_pos + 0);
    float vy = __ldg(view_pos + 1);
    float vz = __ldg(view_pos + 2);

    float px = __ldcs(gb_pos + i * 3 + 0);
    float py = __ldcs(gb_pos + i * 3 + 1);
    float pz = __ldcs(gb_pos + i * 3 + 2);
    float nx = __ldcs(gb_normal + i * 3 + 0);
    float ny = __ldcs(gb_normal + i * 3 + 1);
    float nz = __ldcs(gb_normal + i * 3 + 2);
    float bcx = __ldcs(basecolor + i * 3 + 0);
    float bcy = __ldcs(basecolor + i * 3 + 1);
    float bcz = __ldcs(basecolor + i * 3 + 2);
    float met = __ldcs(metallic + i);
    float rough = __ldcs(roughness + i);

    // wo left unnormalized; only NdotV needs the normalization factor.
    float wx = vx - px, wy = vy - py, wz = vz - pz;
    float wlen2 = fmaxf(wx * wx + wy * wy + wz * wz, 1e-20f);
    float winv = rsqrtf(wlen2);

    float om = 1.0f - met;
    float dax = om * bcx, day = om * bcy, daz = om * bcz;
    float sax = 0.04f * om + met * bcx;
    float say = 0.04f * om + met * bcy;
    float saz = 0.04f * om + met * bcz;

    float d_un = wx * nx + wy * ny + wz * nz;
    float rx = 2.0f * d_un * nx - wx;
    float ry = 2.0f * d_un * ny - wy;
    float rz = 2.0f * d_un * nz - wz;

    // ambient from diffuse cubemap (16^2, fp16 pairs)
    int dface; float du, dv;
    cube_face_uv(nx, ny, nz, dface, du, dv);
    float3x ambient = cube_bilinear_pair(g_diff, 16, dface, du, dv);

    float dlx = ambient.x * dax;
    float dly = ambient.y * day;
    float dlz = ambient.z * daz;

    // FG LUT: one LDG.128 quad record (fp16)
    float NdotV = fmaxf(d_un * winv, 0.0001f);
    float fg0, fg1;
    {
        float tu = NdotV * 256.0f - 0.5f;
        float tv = rough * 256.0f - 0.5f;
        float x0f = floorf(tu);
        float y0f = floorf(tv);
        float fx = tu - x0f;
        if (x0f < 0.0f) fx = 0.0f;
        float fy = tv - y0f;
        if (y0f < 0.0f) fy = 0.0f;
        int x0 = (int)fminf(fmaxf(x0f, 0.0f), 255.0f);
        int y0 = (int)fminf(fmaxf(y0f, 0.0f), 255.0f);
        uint4 e = __ldg(g_fgq + y0 * 256 + x0);
        float2 c00 = __half22float2(*reinterpret_cast<const __half2*>(&e.x));
        float2 c01 = __half22float2(*reinterpret_cast<const __half2*>(&e.y));
        float2 c10 = __half22float2(*reinterpret_cast<const __half2*>(&e.z));
        float2 c11 = __half22float2(*reinterpret_cast<const __half2*>(&e.w));
        float a0 = c00.x + fx * (c01.x - c00.x);
        float b0 = c00.y + fx * (c01.y - c00.y);
        float a1 = c10.x + fx * (c11.x - c10.x);
        float b1 = c10.y + fx * (c11.y - c10.y);
        fg0 = a0 + fy * (a1 - a0);
        fg1 = b0 + fy * (b1 - b0);
    }

    // mip
    float mip;
    {
        const float L = (float)N_MIPS;
        float lo = (fminf(fmaxf(rough, MIN_ROUGHNESS), MAX_ROUGHNESS) - MIN_ROUGHNESS)
                   * ((L - 2.0f) / (MAX_ROUGHNESS - MIN_ROUGHNESS));
        float hi = (fminf(fmaxf(rough, MAX_ROUGHNESS), 1.0f) - MAX_ROUGHNESS)
                   * (1.0f / (1.0f - MAX_ROUGHNESS)) + (L - 2.0f);
        mip = (rough < MAX_ROUGHNESS) ? lo : hi;
        mip = fminf(fmaxf(mip, 0.0f), L - 1.0f);
    }

    int sface; float su, sv;
    cube_face_uv(rx, ry, rz, sface, su, sv);

    int l0 = (int)floorf(mip);
    if (l0 > N_MIPS - 1) l0 = N_MIPS - 1;
    float f = mip - (float)l0;
    int l1 = l0 + 1;
    if (l1 > N_MIPS - 1) l1 = N_MIPS - 1;

    float3x s1 = cube_bilinear_pair(g_spec + PAIR_OFF[l1 - 1], 512 >> l1,
                                    sface, su, sv);
    float3x s0;
    if (l0 == 0) {
        s0 = cube_bilinear_raw(spec0, sface, su, sv);
    } else {
        s0 = cube_bilinear_pair(g_spec + PAIR_OFF[l0 - 1], 512 >> l0,
                                sface, su, sv);
    }

    float spx = s0.x + f * (s1.x - s0.x);
    float spy = s0.y + f * (s1.y - s0.y);
    float spz = s0.z + f * (s1.z - s0.z);

    float refx = sax * fg0 + fg1;
    float refy = say * fg0 + fg1;
    float refz = saz * fg0 + fg1;

    float cx = fminf(fmaxf(spx * refx + dlx, 0.0f), 1.0f);
    float cy = fminf(fmaxf(spy * refy + dly, 0.0f), 1.0f);
    float cz = fminf(fmaxf(spz * refz + dlz, 0.0f), 1.0f);

    __stcs(out + i * 3 + 0, linear2srgb(cx));
    __stcs(out + i * 3 + 1, linear2srgb(cy));
    __stcs(out + i * 3 + 2, linear2srgb(cz));
}

extern "C" void kernel_launch(void* const* d_in, const int* in_sizes, int n_in,
                              void* d_out, int out_size) {
    const float* gb_pos    = (const float*)d_in[0];
    const float* gb_normal = (const float*)d_in[1];
    const float* basecolor = (const float*)d_in[2];
    const float* metallic  = (const float*)d_in[3];
    const float* roughness = (const float*)d_in[4];
    const float* view_pos  = (const float*)d_in[5];
    const float* diffuse   = (const float*)d_in[6];
    const float* fg_lut    = (const float*)d_in[7];

    SpecTable specs;
    specs.p[0] = (const float*)d_in[8];
    specs.p[1] = (const float*)d_in[9];
    specs.p[2] = (const float*)d_in[10];
    specs.p[3] = (const float*)d_in[11];
    specs.p[4] = (const float*)d_in[12];
    specs.p[5] = (const float*)d_in[13];

    float* out = (float*)d_out;
    int n = in_sizes[0] / 3;

    // Pass 1: repack mips 1..5 + diffuse + fg-quad (mip0 stays raw)
    {
        int chunks = PAIR_TOTAL_TEXELS / 4 + DIFF_TEXELS / 4 + FG_TEXELS / 4;
        int threads = 256;
        int blocks = (chunks + threads - 1) / threads;
        repack_kernel<<<blocks, threads>>>(specs, diffuse, fg_lut);
    }

    // Pass 2: shade, 1 px/thread at 6 blocks/SM
    {
        int threads = 256;
        int blocks = (n + threads - 1) / threads;
        envlight_kernel1<<<blocks, threads>>>(gb_pos, gb_normal, basecolor, metallic,
                                              roughness, view_pos, specs.p[0], out, n);
    }
}